// round 14
// baseline (speedup 1.0000x reference)
#include <cuda_runtime.h>
#include <cuda_fp16.h>
#include <cstdint>

#define KDIM 4096
#define NDIM 4096
#define MDIM 8192

// ---------------- scratch (no cudaMalloc allowed) ----------------
__device__ __half g_Gf[(size_t)NDIM * KDIM];         // 32 MB (G rounded to fp16)

// ---------------- prep: build G only (fused T path, 17KB smem, no spills) ----------
__global__ __launch_bounds__(256)
void prep(const float* __restrict__ core0, const float* __restrict__ core1,
          const float* __restrict__ core2) {
    __shared__ float c0s[256];
    __shared__ float Ts[4096];      // T slice [n][m*16+c] for this (i,j)
    int blk = blockIdx.x;
    int ij = blk >> 2; int i = ij >> 4, j = ij & 15;
    int k0 = (blk & 3) * 4;
    int tid = threadIdx.x;
    c0s[tid] = core0[i * 256 + tid];                  // [n][b]
    __syncthreads();
    {   // T[n][mc] = sum_b c0s[n*16+b] * core1[b*4096 + j*256 + mc]
        int mc = tid;
        float c1r[16];
        #pragma unroll
        for (int b = 0; b < 16; ++b) c1r[b] = __ldg(&core1[b * 4096 + j * 256 + mc]);
        #pragma unroll
        for (int n = 0; n < 16; ++n) {
            float s = 0.f;
            #pragma unroll
            for (int b = 0; b < 16; ++b) s += c0s[n * 16 + b] * c1r[b];
            Ts[n * 256 + mc] = s;
        }
    }
    __syncthreads();
    int m = tid >> 4, o = tid & 15;
    #pragma unroll
    for (int k = k0; k < k0 + 4; ++k) {
        float c2r[16];
        #pragma unroll
        for (int c = 0; c < 16; ++c) c2r[c] = __ldg(&core2[c * 256 + k * 16 + o]);
        #pragma unroll
        for (int n = 0; n < 16; ++n) {
            float s = 0.f;
            #pragma unroll
            for (int c = 0; c < 16; ++c) s += Ts[n * 256 + m * 16 + c] * c2r[c];
            size_t idx = (size_t)(i * 256 + j * 16 + k) * 4096 + n * 256 + m * 16 + o;
            g_Gf[idx] = __float2half(s);
        }
    }
}

// ---------------- GEMM, 128-thread CTAs, warp tile 64x64, 2 CTAs/SM ----------
// R14: A converted fp32->fp16 on the fly (LDG->cvt->STS), conv_x prepass deleted.
#define BM 128
#define BN 128
#define BK 64
#define NCH (KDIM / BK)          // 64 chunks
#define S_A 0
#define S_B 16384
#define STAGE_BYTES 32768        // A 16K + B 16K
#define SMEM_BYTES (3 * STAGE_BYTES)   // 96 KB -> 2 CTAs/SM

// rows are 128 bytes (64 fp16); 8 chunks of 16B; XOR swizzle => conflict-free ldmatrix
__device__ __forceinline__ uint32_t swz(int row, int byteInRow) {
    int c = byteInRow >> 4;
    int o = byteInRow & 15;
    return (uint32_t)(row * 128 + (((c ^ row) & 7) << 4) + o);
}
__device__ __forceinline__ void cpa16(uint32_t d, const void* s) {
    asm volatile("cp.async.cg.shared.global [%0], [%1], 16;" :: "r"(d), "l"(s));
}
__device__ __forceinline__ void ldmx4(uint32_t* r, uint32_t addr) {
    asm volatile("ldmatrix.sync.aligned.m8n8.x4.shared.b16 {%0,%1,%2,%3}, [%4];"
                 : "=r"(r[0]), "=r"(r[1]), "=r"(r[2]), "=r"(r[3]) : "r"(addr));
}
__device__ __forceinline__ void mma16816(float* d, const uint32_t* a, uint32_t b0, uint32_t b1) {
    asm volatile(
        "mma.sync.aligned.m16n8k16.row.col.f32.f16.f16.f32 "
        "{%0,%1,%2,%3}, {%4,%5,%6,%7}, {%8,%9}, {%0,%1,%2,%3};\n"
        : "+f"(d[0]), "+f"(d[1]), "+f"(d[2]), "+f"(d[3])
        : "r"(a[0]), "r"(a[1]), "r"(a[2]), "r"(a[3]), "r"(b0), "r"(b1));
}
__device__ __forceinline__ uint32_t packh2(float lo, float hi) {
    __half2 h = __floats2half2_rn(lo, hi);      // low 16 bits <- lo
    return *reinterpret_cast<uint32_t*>(&h);
}

__global__ __launch_bounds__(128, 2)
void gemm_pipe(const float* __restrict__ X, const float* __restrict__ bias,
               float* __restrict__ C) {
    extern __shared__ char smraw[];
    const uint32_t sm0 = (uint32_t)__cvta_generic_to_shared(smraw);

    const int tid = threadIdx.x;
    const int warp = tid >> 5, lane = tid & 31;
    const int wm = warp >> 1, wn = warp & 1;      // 2 m-warps x 2 n-warps, 64x64 each
    const int bn = blockIdx.x, bm = blockIdx.y;

    const float*  Ax = X    + (size_t)bm * BM * KDIM;   // fp32 source
    const __half* Bg = g_Gf + (size_t)bn * BN * KDIM;

    float acc[4][8][4];
    #pragma unroll
    for (int a = 0; a < 4; ++a)
        #pragma unroll
        for (int b = 0; b < 8; ++b)
            #pragma unroll
            for (int c = 0; c < 4; ++c) acc[a][b][c] = 0.f;

    // A quarter: 2 positions/thread, each 32B fp32 -> 16B fp16
    auto ldgAq = [&](int kc, int qt, float4* buf) {
        #pragma unroll
        for (int p = 0; p < 2; ++p) {
            int q = tid + (qt * 2 + p) * 128;
            int row = q >> 3, c = q & 7;
            const float* src = Ax + (size_t)row * KDIM + kc + c * 8;
            buf[p * 2]     = *reinterpret_cast<const float4*>(src);
            buf[p * 2 + 1] = *reinterpret_cast<const float4*>(src + 4);
        }
    };
    auto stsAq = [&](uint32_t sb, int qt, const float4* buf) {
        #pragma unroll
        for (int p = 0; p < 2; ++p) {
            int q = tid + (qt * 2 + p) * 128;
            int row = q >> 3, c = q & 7;
            uint32_t d = sb + S_A + swz(row, c * 16);
            uint32_t r0 = packh2(buf[p * 2].x,     buf[p * 2].y);
            uint32_t r1 = packh2(buf[p * 2].z,     buf[p * 2].w);
            uint32_t r2 = packh2(buf[p * 2 + 1].x, buf[p * 2 + 1].y);
            uint32_t r3 = packh2(buf[p * 2 + 1].z, buf[p * 2 + 1].w);
            asm volatile("st.shared.v4.b32 [%0], {%1,%2,%3,%4};"
                         :: "r"(d), "r"(r0), "r"(r1), "r"(r2), "r"(r3));
        }
    };
    auto loadBq = [&](int kc, uint32_t sb, int qt) {
        #pragma unroll
        for (int t = qt * 2; t < qt * 2 + 2; ++t) {
            int q = tid + t * 128;
            int row = q >> 3, c = q & 7;
            cpa16(sb + S_B + swz(row, c * 16),
                  (const char*)(Bg + (size_t)row * KDIM + kc) + c * 16);
        }
    };
    auto loadAfrag = [&](uint32_t (*dst)[4], uint32_t sb, int kk) {
        #pragma unroll
        for (int im = 0; im < 4; ++im) {
            int row = wm * 64 + im * 16 + (lane & 15);
            int byte = kk * 2 + ((lane >> 4) << 4);
            ldmx4(dst[im], sb + S_A + swz(row, byte));
        }
    };
    auto loadBfrag = [&](uint32_t* dst, uint32_t sb, int kk, int jp) {
        int nrow = wn * 64 + (jp * 2 + (lane >> 4)) * 8 + (lane & 7);
        int byte = kk * 2 + (((lane >> 3) & 1) << 4);
        ldmx4(dst, sb + S_B + swz(nrow, byte));
    };

    // prologue: stages 0,1 — A direct LDG/cvt/STS, B cp.async
    #pragma unroll
    for (int s = 0; s < 2; ++s) {
        int kc = s * BK;
        uint32_t sb = sm0 + (uint32_t)s * STAGE_BYTES;
        float4 buf[4];
        #pragma unroll
        for (int qt = 0; qt < 4; ++qt) { ldgAq(kc, qt, buf); stsAq(sb, qt, buf); }
        #pragma unroll
        for (int qt = 0; qt < 4; ++qt) loadBq(kc, sb, qt);
        asm volatile("cp.async.commit_group;");
    }

    int cur = 0, nxt = 2;
    for (int ch = 0; ch < NCH; ++ch) {
        asm volatile("cp.async.wait_group 1;");
        __syncthreads();

        const uint32_t sb = sm0 + (uint32_t)cur * STAGE_BYTES;
        const bool doLoad = (ch + 2 < NCH);
        const int ldkc = (ch + 2) * BK;
        const uint32_t ldsb = sm0 + (uint32_t)nxt * STAGE_BYTES;
        cur = (cur == 2) ? 0 : cur + 1;
        nxt = (nxt == 2) ? 0 : nxt + 1;

        float4 pa0[4], pa1[4];
        if (doLoad) ldgAq(ldkc, 0, pa0);          // LDG q0
        #pragma unroll
        for (int kki = 0; kki < 4; ++kki) {
            if (doLoad) {
                if (kki == 0)      { ldgAq(ldkc, 1, pa1); }
                else if (kki == 1) { stsAq(ldsb, 0, pa0); ldgAq(ldkc, 2, pa0); }
                else if (kki == 2) { stsAq(ldsb, 1, pa1); ldgAq(ldkc, 3, pa1); }
                else               { stsAq(ldsb, 2, pa0); }
                loadBq(ldkc, ldsb, kki);
            }
            if (kki == 3) asm volatile("cp.async.commit_group;");

            const int kk = kki * 16;
            uint32_t av[4][4];
            loadAfrag(av, sb, kk);
            #pragma unroll
            for (int jp = 0; jp < 4; ++jp) {
                uint32_t bv[4];
                loadBfrag(bv, sb, kk, jp);
                #pragma unroll
                for (int im = 0; im < 4; ++im) {
                    mma16816(acc[im][jp * 2],     av[im], bv[0], bv[1]);
                    mma16816(acc[im][jp * 2 + 1], av[im], bv[2], bv[3]);
                }
            }
        }
        if (doLoad) stsAq(ldsb, 3, pa1);          // STS q3 (data long since arrived)
    }

    // ---- epilogue: add bias, store fp32 ----
    #pragma unroll
    for (int im = 0; im < 4; ++im) {
        int r0 = bm * BM + wm * 64 + im * 16 + (lane >> 2);
        #pragma unroll
        for (int jn = 0; jn < 8; ++jn) {
            int cb = bn * BN + wn * 64 + jn * 8 + (lane & 3) * 2;
            float b0 = bias[cb], b1 = bias[cb + 1];
            float2 v0, v1;
            v0.x = acc[im][jn][0] + b0; v0.y = acc[im][jn][1] + b1;
            v1.x = acc[im][jn][2] + b0; v1.y = acc[im][jn][3] + b1;
            *reinterpret_cast<float2*>(C + (size_t)r0 * NDIM + cb) = v0;
            *reinterpret_cast<float2*>(C + (size_t)(r0 + 8) * NDIM + cb) = v1;
        }
    }
}

// ---------------- launch ----------------
extern "C" void kernel_launch(void* const* d_in, const int* in_sizes, int n_in,
                              void* d_out, int out_size) {
    const float* x     = (const float*)d_in[0];
    const float* core0 = (const float*)d_in[1];
    const float* core1 = (const float*)d_in[2];
    const float* core2 = (const float*)d_in[3];
    const float* bias  = (const float*)d_in[4];
    float* out = (float*)d_out;

    prep<<<1024, 256>>>(core0, core1, core2);

    cudaFuncSetAttribute(gemm_pipe, cudaFuncAttributeMaxDynamicSharedMemorySize, SMEM_BYTES);
    dim3 grid(NDIM / BN, MDIM / BM);     // (32, 64), x-fastest keeps G hot in L2
    gemm_pipe<<<grid, 128, SMEM_BYTES>>>(x, bias, out);
}

// round 15
// speedup vs baseline: 1.0006x; 1.0006x over previous
#include <cuda_runtime.h>
#include <cuda_fp16.h>
#include <cstdint>

#define KDIM 4096
#define NDIM 4096
#define MDIM 8192

// ---------------- scratch (no cudaMalloc allowed) ----------------
__device__ __half g_Gf[(size_t)NDIM * KDIM];         // 32 MB (G rounded to fp16)

// ---------------- prep: build G only (fused T path, 17KB smem, no spills) ----------
__global__ __launch_bounds__(256)
void prep(const float* __restrict__ core0, const float* __restrict__ core1,
          const float* __restrict__ core2) {
    __shared__ float c0s[256];
    __shared__ float Ts[4096];      // T slice [n][m*16+c] for this (i,j)
    int blk = blockIdx.x;
    int ij = blk >> 2; int i = ij >> 4, j = ij & 15;
    int k0 = (blk & 3) * 4;
    int tid = threadIdx.x;
    c0s[tid] = core0[i * 256 + tid];                  // [n][b]
    __syncthreads();
    {   // T[n][mc] = sum_b c0s[n*16+b] * core1[b*4096 + j*256 + mc]
        int mc = tid;
        float c1r[16];
        #pragma unroll
        for (int b = 0; b < 16; ++b) c1r[b] = __ldg(&core1[b * 4096 + j * 256 + mc]);
        #pragma unroll
        for (int n = 0; n < 16; ++n) {
            float s = 0.f;
            #pragma unroll
            for (int b = 0; b < 16; ++b) s += c0s[n * 16 + b] * c1r[b];
            Ts[n * 256 + mc] = s;
        }
    }
    __syncthreads();
    int m = tid >> 4, o = tid & 15;
    #pragma unroll
    for (int k = k0; k < k0 + 4; ++k) {
        float c2r[16];
        #pragma unroll
        for (int c = 0; c < 16; ++c) c2r[c] = __ldg(&core2[c * 256 + k * 16 + o]);
        #pragma unroll
        for (int n = 0; n < 16; ++n) {
            float s = 0.f;
            #pragma unroll
            for (int c = 0; c < 16; ++c) s += Ts[n * 256 + m * 16 + c] * c2r[c];
            size_t idx = (size_t)(i * 256 + j * 16 + k) * 4096 + n * 256 + m * 16 + o;
            g_Gf[idx] = __float2half(s);
        }
    }
}

// ---------------- GEMM, 128-thread CTAs, warp tile 64x64, 2 CTAs/SM ----------
// R14: A converted fp32->fp16 on the fly (LDG->cvt->STS), conv_x prepass deleted.
#define BM 128
#define BN 128
#define BK 64
#define NCH (KDIM / BK)          // 64 chunks
#define S_A 0
#define S_B 16384
#define STAGE_BYTES 32768        // A 16K + B 16K
#define SMEM_BYTES (3 * STAGE_BYTES)   // 96 KB -> 2 CTAs/SM

// rows are 128 bytes (64 fp16); 8 chunks of 16B; XOR swizzle => conflict-free ldmatrix
__device__ __forceinline__ uint32_t swz(int row, int byteInRow) {
    int c = byteInRow >> 4;
    int o = byteInRow & 15;
    return (uint32_t)(row * 128 + (((c ^ row) & 7) << 4) + o);
}
__device__ __forceinline__ void cpa16(uint32_t d, const void* s) {
    asm volatile("cp.async.cg.shared.global [%0], [%1], 16;" :: "r"(d), "l"(s));
}
__device__ __forceinline__ void ldmx4(uint32_t* r, uint32_t addr) {
    asm volatile("ldmatrix.sync.aligned.m8n8.x4.shared.b16 {%0,%1,%2,%3}, [%4];"
                 : "=r"(r[0]), "=r"(r[1]), "=r"(r[2]), "=r"(r[3]) : "r"(addr));
}
__device__ __forceinline__ void mma16816(float* d, const uint32_t* a, uint32_t b0, uint32_t b1) {
    asm volatile(
        "mma.sync.aligned.m16n8k16.row.col.f32.f16.f16.f32 "
        "{%0,%1,%2,%3}, {%4,%5,%6,%7}, {%8,%9}, {%0,%1,%2,%3};\n"
        : "+f"(d[0]), "+f"(d[1]), "+f"(d[2]), "+f"(d[3])
        : "r"(a[0]), "r"(a[1]), "r"(a[2]), "r"(a[3]), "r"(b0), "r"(b1));
}
__device__ __forceinline__ uint32_t packh2(float lo, float hi) {
    __half2 h = __floats2half2_rn(lo, hi);      // low 16 bits <- lo
    return *reinterpret_cast<uint32_t*>(&h);
}

__global__ __launch_bounds__(128, 2)
void gemm_pipe(const float* __restrict__ X, const float* __restrict__ bias,
               float* __restrict__ C) {
    extern __shared__ char smraw[];
    const uint32_t sm0 = (uint32_t)__cvta_generic_to_shared(smraw);

    const int tid = threadIdx.x;
    const int warp = tid >> 5, lane = tid & 31;
    const int wm = warp >> 1, wn = warp & 1;      // 2 m-warps x 2 n-warps, 64x64 each
    const int bn = blockIdx.x, bm = blockIdx.y;

    const float*  Ax = X    + (size_t)bm * BM * KDIM;   // fp32 source
    const __half* Bg = g_Gf + (size_t)bn * BN * KDIM;

    float acc[4][8][4];
    #pragma unroll
    for (int a = 0; a < 4; ++a)
        #pragma unroll
        for (int b = 0; b < 8; ++b)
            #pragma unroll
            for (int c = 0; c < 4; ++c) acc[a][b][c] = 0.f;

    // A quarter: 2 positions/thread, each 32B fp32 -> 16B fp16
    auto ldgAq = [&](int kc, int qt, float4* buf) {
        #pragma unroll
        for (int p = 0; p < 2; ++p) {
            int q = tid + (qt * 2 + p) * 128;
            int row = q >> 3, c = q & 7;
            const float* src = Ax + (size_t)row * KDIM + kc + c * 8;
            buf[p * 2]     = *reinterpret_cast<const float4*>(src);
            buf[p * 2 + 1] = *reinterpret_cast<const float4*>(src + 4);
        }
    };
    auto stsAq = [&](uint32_t sb, int qt, const float4* buf) {
        #pragma unroll
        for (int p = 0; p < 2; ++p) {
            int q = tid + (qt * 2 + p) * 128;
            int row = q >> 3, c = q & 7;
            uint32_t d = sb + S_A + swz(row, c * 16);
            uint32_t r0 = packh2(buf[p * 2].x,     buf[p * 2].y);
            uint32_t r1 = packh2(buf[p * 2].z,     buf[p * 2].w);
            uint32_t r2 = packh2(buf[p * 2 + 1].x, buf[p * 2 + 1].y);
            uint32_t r3 = packh2(buf[p * 2 + 1].z, buf[p * 2 + 1].w);
            asm volatile("st.shared.v4.b32 [%0], {%1,%2,%3,%4};"
                         :: "r"(d), "r"(r0), "r"(r1), "r"(r2), "r"(r3));
        }
    };
    auto loadBq = [&](int kc, uint32_t sb, int qt) {
        #pragma unroll
        for (int t = qt * 2; t < qt * 2 + 2; ++t) {
            int q = tid + t * 128;
            int row = q >> 3, c = q & 7;
            cpa16(sb + S_B + swz(row, c * 16),
                  (const char*)(Bg + (size_t)row * KDIM + kc) + c * 16);
        }
    };
    auto loadAfrag = [&](uint32_t (*dst)[4], uint32_t sb, int kk) {
        #pragma unroll
        for (int im = 0; im < 4; ++im) {
            int row = wm * 64 + im * 16 + (lane & 15);
            int byte = kk * 2 + ((lane >> 4) << 4);
            ldmx4(dst[im], sb + S_A + swz(row, byte));
        }
    };
    auto loadBfrag = [&](uint32_t* dst, uint32_t sb, int kk, int jp) {
        int nrow = wn * 64 + (jp * 2 + (lane >> 4)) * 8 + (lane & 7);
        int byte = kk * 2 + (((lane >> 3) & 1) << 4);
        ldmx4(dst, sb + S_B + swz(nrow, byte));
    };

    // prologue: stages 0,1 — A direct LDG/cvt/STS, B cp.async
    #pragma unroll
    for (int s = 0; s < 2; ++s) {
        int kc = s * BK;
        uint32_t sb = sm0 + (uint32_t)s * STAGE_BYTES;
        float4 buf[4];
        #pragma unroll
        for (int qt = 0; qt < 4; ++qt) { ldgAq(kc, qt, buf); stsAq(sb, qt, buf); }
        #pragma unroll
        for (int qt = 0; qt < 4; ++qt) loadBq(kc, sb, qt);
        asm volatile("cp.async.commit_group;");
    }

    int cur = 0, nxt = 2;
    for (int ch = 0; ch < NCH; ++ch) {
        asm volatile("cp.async.wait_group 1;");
        __syncthreads();

        const uint32_t sb = sm0 + (uint32_t)cur * STAGE_BYTES;
        const bool doLoad = (ch + 2 < NCH);
        const int ldkc = (ch + 2) * BK;
        const uint32_t ldsb = sm0 + (uint32_t)nxt * STAGE_BYTES;
        cur = (cur == 2) ? 0 : cur + 1;
        nxt = (nxt == 2) ? 0 : nxt + 1;

        float4 pa0[4], pa1[4];
        if (doLoad) ldgAq(ldkc, 0, pa0);          // LDG q0
        #pragma unroll
        for (int kki = 0; kki < 4; ++kki) {
            if (doLoad) {
                if (kki == 0)      { ldgAq(ldkc, 1, pa1); }
                else if (kki == 1) { stsAq(ldsb, 0, pa0); ldgAq(ldkc, 2, pa0); }
                else if (kki == 2) { stsAq(ldsb, 1, pa1); ldgAq(ldkc, 3, pa1); }
                else               { stsAq(ldsb, 2, pa0); }
                loadBq(ldkc, ldsb, kki);
            }
            if (kki == 3) asm volatile("cp.async.commit_group;");

            const int kk = kki * 16;
            uint32_t av[4][4];
            loadAfrag(av, sb, kk);
            #pragma unroll
            for (int jp = 0; jp < 4; ++jp) {
                uint32_t bv[4];
                loadBfrag(bv, sb, kk, jp);
                #pragma unroll
                for (int im = 0; im < 4; ++im) {
                    mma16816(acc[im][jp * 2],     av[im], bv[0], bv[1]);
                    mma16816(acc[im][jp * 2 + 1], av[im], bv[2], bv[3]);
                }
            }
        }
        if (doLoad) stsAq(ldsb, 3, pa1);          // STS q3 (data long since arrived)
    }

    // ---- epilogue: add bias, store fp32 ----
    #pragma unroll
    for (int im = 0; im < 4; ++im) {
        int r0 = bm * BM + wm * 64 + im * 16 + (lane >> 2);
        #pragma unroll
        for (int jn = 0; jn < 8; ++jn) {
            int cb = bn * BN + wn * 64 + jn * 8 + (lane & 3) * 2;
            float b0 = bias[cb], b1 = bias[cb + 1];
            float2 v0, v1;
            v0.x = acc[im][jn][0] + b0; v0.y = acc[im][jn][1] + b1;
            v1.x = acc[im][jn][2] + b0; v1.y = acc[im][jn][3] + b1;
            *reinterpret_cast<float2*>(C + (size_t)r0 * NDIM + cb) = v0;
            *reinterpret_cast<float2*>(C + (size_t)(r0 + 8) * NDIM + cb) = v1;
        }
    }
}

// ---------------- launch ----------------
extern "C" void kernel_launch(void* const* d_in, const int* in_sizes, int n_in,
                              void* d_out, int out_size) {
    const float* x     = (const float*)d_in[0];
    const float* core0 = (const float*)d_in[1];
    const float* core1 = (const float*)d_in[2];
    const float* core2 = (const float*)d_in[3];
    const float* bias  = (const float*)d_in[4];
    float* out = (float*)d_out;

    prep<<<1024, 256>>>(core0, core1, core2);

    cudaFuncSetAttribute(gemm_pipe, cudaFuncAttributeMaxDynamicSharedMemorySize, SMEM_BYTES);
    dim3 grid(NDIM / BN, MDIM / BM);     // (32, 64), x-fastest keeps G hot in L2
    gemm_pipe<<<grid, 128, SMEM_BYTES>>>(x, bias, out);
}

// round 16
// speedup vs baseline: 1.4040x; 1.4032x over previous
#include <cuda_runtime.h>
#include <cuda_fp16.h>
#include <cstdint>

#define KDIM 4096
#define NDIM 4096
#define MDIM 8192

// ---------------- scratch (no cudaMalloc allowed) ----------------
__device__ __half g_Gf[(size_t)NDIM * KDIM];         // 32 MB (G rounded to fp16)
__device__ __half g_xf[(size_t)MDIM * KDIM];         // 64 MB (x rounded to fp16)

// ---------------- fused prep ----------------
// blocks [0,1024): build G (fused T path, 17KB smem, no spills)
// blocks [1024, 1024+2048): convert x, 16 float4 per thread (high MLP, streaming)
#define NB_CONV 2048
__global__ __launch_bounds__(256)
void prep(const float* __restrict__ core0, const float* __restrict__ core1,
          const float* __restrict__ core2, const float* __restrict__ x) {
    int blk = blockIdx.x;
    if (blk < 1024) {
        __shared__ float c0s[256];
        __shared__ float Ts[4096];      // T slice [n][m*16+c] for this (i,j)
        int ij = blk >> 2; int i = ij >> 4, j = ij & 15;
        int k0 = (blk & 3) * 4;
        int tid = threadIdx.x;
        c0s[tid] = core0[i * 256 + tid];                  // [n][b]
        __syncthreads();
        {   // T[n][mc] = sum_b c0s[n*16+b] * core1[b*4096 + j*256 + mc]
            int mc = tid;
            float c1r[16];
            #pragma unroll
            for (int b = 0; b < 16; ++b) c1r[b] = __ldg(&core1[b * 4096 + j * 256 + mc]);
            #pragma unroll
            for (int n = 0; n < 16; ++n) {
                float s = 0.f;
                #pragma unroll
                for (int b = 0; b < 16; ++b) s += c0s[n * 16 + b] * c1r[b];
                Ts[n * 256 + mc] = s;
            }
        }
        __syncthreads();
        int m = tid >> 4, o = tid & 15;
        #pragma unroll
        for (int k = k0; k < k0 + 4; ++k) {
            float c2r[16];
            #pragma unroll
            for (int c = 0; c < 16; ++c) c2r[c] = __ldg(&core2[c * 256 + k * 16 + o]);
            #pragma unroll
            for (int n = 0; n < 16; ++n) {
                float s = 0.f;
                #pragma unroll
                for (int c = 0; c < 16; ++c) s += Ts[n * 256 + m * 16 + c] * c2r[c];
                size_t idx = (size_t)(i * 256 + j * 16 + k) * 4096 + n * 256 + m * 16 + o;
                g_Gf[idx] = __float2half(s);
            }
        }
    } else {
        // ---- conv_x: 16 float4 per thread, streaming hints (don't evict G from L2) ----
        const float4* xin = reinterpret_cast<const float4*>(x);
        uint2* xout = reinterpret_cast<uint2*>(g_xf);
        size_t base = (size_t)(blk - 1024) * 4096 + threadIdx.x;
        #pragma unroll
        for (int t = 0; t < 16; ++t) {
            size_t i = base + (size_t)t * 256;
            float4 v = __ldcs(&xin[i]);
            uint2 hp;
            hp.x = (uint32_t)__half_as_ushort(__float2half(v.x)) |
                   ((uint32_t)__half_as_ushort(__float2half(v.y)) << 16);
            hp.y = (uint32_t)__half_as_ushort(__float2half(v.z)) |
                   ((uint32_t)__half_as_ushort(__float2half(v.w)) << 16);
            __stcs(&xout[i], hp);
        }
    }
}

// ---------------- GEMM, 128-thread CTAs, warp tile 64x64, 2 CTAs/SM (R13 frozen) -----
#define BM 128
#define BN 128
#define BK 64
#define NCH (KDIM / BK)          // 64 chunks
#define S_A 0
#define S_B 16384
#define STAGE_BYTES 32768        // A 16K + B 16K
#define SMEM_BYTES (3 * STAGE_BYTES)   // 96 KB -> 2 CTAs/SM

// rows are 128 bytes (64 fp16); 8 chunks of 16B; XOR swizzle => conflict-free ldmatrix
__device__ __forceinline__ uint32_t swz(int row, int byteInRow) {
    int c = byteInRow >> 4;
    int o = byteInRow & 15;
    return (uint32_t)(row * 128 + (((c ^ row) & 7) << 4) + o);
}
__device__ __forceinline__ void cpa16(uint32_t d, const void* s) {
    asm volatile("cp.async.cg.shared.global [%0], [%1], 16;" :: "r"(d), "l"(s));
}
__device__ __forceinline__ void ldmx4(uint32_t* r, uint32_t addr) {
    asm volatile("ldmatrix.sync.aligned.m8n8.x4.shared.b16 {%0,%1,%2,%3}, [%4];"
                 : "=r"(r[0]), "=r"(r[1]), "=r"(r[2]), "=r"(r[3]) : "r"(addr));
}
__device__ __forceinline__ void mma16816(float* d, const uint32_t* a, uint32_t b0, uint32_t b1) {
    asm volatile(
        "mma.sync.aligned.m16n8k16.row.col.f32.f16.f16.f32 "
        "{%0,%1,%2,%3}, {%4,%5,%6,%7}, {%8,%9}, {%0,%1,%2,%3};\n"
        : "+f"(d[0]), "+f"(d[1]), "+f"(d[2]), "+f"(d[3])
        : "r"(a[0]), "r"(a[1]), "r"(a[2]), "r"(a[3]), "r"(b0), "r"(b1));
}

__global__ __launch_bounds__(128, 2)
void gemm_pipe(const float* __restrict__ bias, float* __restrict__ C) {
    extern __shared__ char smraw[];
    const uint32_t sm0 = (uint32_t)__cvta_generic_to_shared(smraw);

    const int tid = threadIdx.x;
    const int warp = tid >> 5, lane = tid & 31;
    const int wm = warp >> 1, wn = warp & 1;      // 2 m-warps x 2 n-warps, 64x64 each
    const int bn = blockIdx.x, bm = blockIdx.y;

    const __half* Ax = g_xf + (size_t)bm * BM * KDIM;
    const __half* Bg = g_Gf + (size_t)bn * BN * KDIM;

    float acc[4][8][4];
    #pragma unroll
    for (int a = 0; a < 4; ++a)
        #pragma unroll
        for (int b = 0; b < 8; ++b)
            #pragma unroll
            for (int c = 0; c < 4; ++c) acc[a][b][c] = 0.f;

    auto loadStage = [&](int ch, int st) {        // full stage (prologue only)
        const uint32_t sb = sm0 + (uint32_t)st * STAGE_BYTES;
        const int kc = ch * BK;
        #pragma unroll
        for (int t = 0; t < 8; ++t) {
            int q = tid + t * 128;
            int row = q >> 3, c = q & 7;
            cpa16(sb + S_A + swz(row, c * 16),
                  (const char*)(Ax + (size_t)row * KDIM + kc) + c * 16);
        }
        #pragma unroll
        for (int t = 0; t < 8; ++t) {
            int q = tid + t * 128;
            int row = q >> 3, c = q & 7;
            cpa16(sb + S_B + swz(row, c * 16),
                  (const char*)(Bg + (size_t)row * KDIM + kc) + c * 16);
        }
    };

    auto loadQuarter = [&](int ch, int st, int qt) {   // 1/4 of a stage (2 A + 2 B iters)
        const uint32_t sb = sm0 + (uint32_t)st * STAGE_BYTES;
        const int kc = ch * BK;
        #pragma unroll
        for (int t = qt * 2; t < qt * 2 + 2; ++t) {
            int q = tid + t * 128;
            int row = q >> 3, c = q & 7;
            cpa16(sb + S_A + swz(row, c * 16),
                  (const char*)(Ax + (size_t)row * KDIM + kc) + c * 16);
        }
        #pragma unroll
        for (int t = qt * 2; t < qt * 2 + 2; ++t) {
            int q = tid + t * 128;
            int row = q >> 3, c = q & 7;
            cpa16(sb + S_B + swz(row, c * 16),
                  (const char*)(Bg + (size_t)row * KDIM + kc) + c * 16);
        }
    };

    auto loadAfrag = [&](uint32_t (*dst)[4], uint32_t sb, int kk) {
        #pragma unroll
        for (int im = 0; im < 4; ++im) {
            int row = wm * 64 + im * 16 + (lane & 15);
            int byte = kk * 2 + ((lane >> 4) << 4);
            ldmx4(dst[im], sb + S_A + swz(row, byte));
        }
    };
    auto loadBfrag = [&](uint32_t* dst, uint32_t sb, int kk, int jp) {
        int nrow = wn * 64 + (jp * 2 + (lane >> 4)) * 8 + (lane & 7);
        int byte = kk * 2 + (((lane >> 3) & 1) << 4);
        ldmx4(dst, sb + S_B + swz(nrow, byte));
    };

    // prologue: stages 0,1
    loadStage(0, 0);
    asm volatile("cp.async.commit_group;");
    loadStage(1, 1);
    asm volatile("cp.async.commit_group;");

    int cur = 0, nxt = 2;
    for (int ch = 0; ch < NCH; ++ch) {
        asm volatile("cp.async.wait_group 1;");
        __syncthreads();

        const uint32_t sb = sm0 + (uint32_t)cur * STAGE_BYTES;
        const bool doLoad = (ch + 2 < NCH);
        const int ldch = ch + 2, ldst = nxt;
        cur = (cur == 2) ? 0 : cur + 1;
        nxt = (nxt == 2) ? 0 : nxt + 1;

        uint32_t avA[4][4], avB[4][4];
        uint32_t bvA[4], bvB[4];
        loadAfrag(avA, sb, 0);                    // prefetch A for kk=0
        loadBfrag(bvA, sb, 0, 0);                 // prefetch B for kk=0, jp=0
        #pragma unroll
        for (int kki = 0; kki < 4; ++kki) {
            if (doLoad) loadQuarter(ldch, ldst, kki);      // spread next-stage loads
            if (kki == 3) asm volatile("cp.async.commit_group;");
            uint32_t (*avc)[4] = (kki & 1) ? avB : avA;
            uint32_t (*avn)[4] = (kki & 1) ? avA : avB;
            if (kki < 3) loadAfrag(avn, sb, (kki + 1) * 16);   // prefetch next k16 A
            const int kk = kki * 16;
            #pragma unroll
            for (int jp = 0; jp < 4; ++jp) {
                uint32_t* bvc = ((kki * 4 + jp) & 1) ? bvB : bvA;
                uint32_t* bvn = ((kki * 4 + jp) & 1) ? bvA : bvB;
                if (jp < 3)            loadBfrag(bvn, sb, kk, jp + 1);
                else if (kki < 3)      loadBfrag(bvn, sb, kk + 16, 0);
                #pragma unroll
                for (int im = 0; im < 4; ++im) {
                    mma16816(acc[im][jp * 2],     avc[im], bvc[0], bvc[1]);
                    mma16816(acc[im][jp * 2 + 1], avc[im], bvc[2], bvc[3]);
                }
            }
        }
    }

    // ---- epilogue: add bias, store fp32 ----
    #pragma unroll
    for (int im = 0; im < 4; ++im) {
        int r0 = bm * BM + wm * 64 + im * 16 + (lane >> 2);
        #pragma unroll
        for (int jn = 0; jn < 8; ++jn) {
            int cb = bn * BN + wn * 64 + jn * 8 + (lane & 3) * 2;
            float b0 = bias[cb], b1 = bias[cb + 1];
            float2 v0, v1;
            v0.x = acc[im][jn][0] + b0; v0.y = acc[im][jn][1] + b1;
            v1.x = acc[im][jn][2] + b0; v1.y = acc[im][jn][3] + b1;
            *reinterpret_cast<float2*>(C + (size_t)r0 * NDIM + cb) = v0;
            *reinterpret_cast<float2*>(C + (size_t)(r0 + 8) * NDIM + cb) = v1;
        }
    }
}

// ---------------- launch ----------------
extern "C" void kernel_launch(void* const* d_in, const int* in_sizes, int n_in,
                              void* d_out, int out_size) {
    const float* x     = (const float*)d_in[0];
    const float* core0 = (const float*)d_in[1];
    const float* core1 = (const float*)d_in[2];
    const float* core2 = (const float*)d_in[3];
    const float* bias  = (const float*)d_in[4];
    float* out = (float*)d_out;

    // 1024 build-G blocks (k split 4-ways) + 2048 conv blocks (16 float4/thread)
    prep<<<1024 + NB_CONV, 256>>>(core0, core1, core2, x);

    cudaFuncSetAttribute(gemm_pipe, cudaFuncAttributeMaxDynamicSharedMemorySize, SMEM_BYTES);
    dim3 grid(NDIM / BN, MDIM / BM);     // (32, 64), x-fastest keeps G hot in L2
    gemm_pipe<<<grid, 128, SMEM_BYTES>>>(bias, out);
}

// round 17
// speedup vs baseline: 1.6033x; 1.1419x over previous
#include <cuda_runtime.h>
#include <cuda_fp16.h>
#include <cstdint>

#define KDIM 4096
#define NDIM 4096
#define MDIM 8192

// ---------------- scratch (no cudaMalloc allowed) ----------------
__device__ __half g_Gf[(size_t)NDIM * KDIM];         // 32 MB (G rounded to fp16)
__device__ __half g_xf[(size_t)MDIM * KDIM];         // 64 MB (x rounded to fp16)

// ---------------- fused prep ----------------
// blocks [0,1024): build G (fused T path, 17KB smem, no spills)
// blocks [1024, 1024+2048): convert x, 16 float4 per thread (high MLP)
#define NB_CONV 2048
__global__ __launch_bounds__(256)
void prep(const float* __restrict__ core0, const float* __restrict__ core1,
          const float* __restrict__ core2, const float* __restrict__ x) {
    int blk = blockIdx.x;
    if (blk < 1024) {
        __shared__ float c0s[256];
        __shared__ float Ts[4096];      // T slice [n][m*16+c] for this (i,j)
        int ij = blk >> 2; int i = ij >> 4, j = ij & 15;
        int k0 = (blk & 3) * 4;
        int tid = threadIdx.x;
        c0s[tid] = core0[i * 256 + tid];                  // [n][b]
        __syncthreads();
        {   // T[n][mc] = sum_b c0s[n*16+b] * core1[b*4096 + j*256 + mc]
            int mc = tid;
            float c1r[16];
            #pragma unroll
            for (int b = 0; b < 16; ++b) c1r[b] = __ldg(&core1[b * 4096 + j * 256 + mc]);
            #pragma unroll
            for (int n = 0; n < 16; ++n) {
                float s = 0.f;
                #pragma unroll
                for (int b = 0; b < 16; ++b) s += c0s[n * 16 + b] * c1r[b];
                Ts[n * 256 + mc] = s;
            }
        }
        __syncthreads();
        int m = tid >> 4, o = tid & 15;
        #pragma unroll
        for (int k = k0; k < k0 + 4; ++k) {
            float c2r[16];
            #pragma unroll
            for (int c = 0; c < 16; ++c) c2r[c] = __ldg(&core2[c * 256 + k * 16 + o]);
            #pragma unroll
            for (int n = 0; n < 16; ++n) {
                float s = 0.f;
                #pragma unroll
                for (int c = 0; c < 16; ++c) s += Ts[n * 256 + m * 16 + c] * c2r[c];
                size_t idx = (size_t)(i * 256 + j * 16 + k) * 4096 + n * 256 + m * 16 + o;
                g_Gf[idx] = __float2half(s);
            }
        }
    } else {
        // ---- conv_x: 16 float4 per thread, 4096 float4 per block ----
        const float4* xin = reinterpret_cast<const float4*>(x);
        uint2* xout = reinterpret_cast<uint2*>(g_xf);
        size_t base = (size_t)(blk - 1024) * 4096 + threadIdx.x;
        #pragma unroll
        for (int t = 0; t < 16; ++t) {
            size_t i = base + (size_t)t * 256;
            float4 v = xin[i];
            uint2 hp;
            hp.x = (uint32_t)__half_as_ushort(__float2half(v.x)) |
                   ((uint32_t)__half_as_ushort(__float2half(v.y)) << 16);
            hp.y = (uint32_t)__half_as_ushort(__float2half(v.z)) |
                   ((uint32_t)__half_as_ushort(__float2half(v.w)) << 16);
            xout[i] = hp;
        }
    }
}

// ---------------- GEMM, 128-thread CTAs, warp tile 64x64, 2 CTAs/SM ----------
// Quarter-spread next-stage cp.async (one quarter per k16 step).
#define BM 128
#define BN 128
#define BK 64
#define NCH (KDIM / BK)          // 64 chunks
#define S_A 0
#define S_B 16384
#define STAGE_BYTES 32768        // A 16K + B 16K
#define SMEM_BYTES (3 * STAGE_BYTES)   // 96 KB -> 2 CTAs/SM

// rows are 128 bytes (64 fp16); 8 chunks of 16B; XOR swizzle => conflict-free ldmatrix
__device__ __forceinline__ uint32_t swz(int row, int byteInRow) {
    int c = byteInRow >> 4;
    int o = byteInRow & 15;
    return (uint32_t)(row * 128 + (((c ^ row) & 7) << 4) + o);
}
__device__ __forceinline__ void cpa16(uint32_t d, const void* s) {
    asm volatile("cp.async.cg.shared.global [%0], [%1], 16;" :: "r"(d), "l"(s));
}
__device__ __forceinline__ void ldmx4(uint32_t* r, uint32_t addr) {
    asm volatile("ldmatrix.sync.aligned.m8n8.x4.shared.b16 {%0,%1,%2,%3}, [%4];"
                 : "=r"(r[0]), "=r"(r[1]), "=r"(r[2]), "=r"(r[3]) : "r"(addr));
}
__device__ __forceinline__ void mma16816(float* d, const uint32_t* a, uint32_t b0, uint32_t b1) {
    asm volatile(
        "mma.sync.aligned.m16n8k16.row.col.f32.f16.f16.f32 "
        "{%0,%1,%2,%3}, {%4,%5,%6,%7}, {%8,%9}, {%0,%1,%2,%3};\n"
        : "+f"(d[0]), "+f"(d[1]), "+f"(d[2]), "+f"(d[3])
        : "r"(a[0]), "r"(a[1]), "r"(a[2]), "r"(a[3]), "r"(b0), "r"(b1));
}

__global__ __launch_bounds__(128, 2)
void gemm_pipe(const float* __restrict__ bias, float* __restrict__ C) {
    extern __shared__ char smraw[];
    const uint32_t sm0 = (uint32_t)__cvta_generic_to_shared(smraw);

    const int tid = threadIdx.x;
    const int warp = tid >> 5, lane = tid & 31;
    const int wm = warp >> 1, wn = warp & 1;      // 2 m-warps x 2 n-warps, 64x64 each
    const int bn = blockIdx.x, bm = blockIdx.y;

    const __half* Ax = g_xf + (size_t)bm * BM * KDIM;
    const __half* Bg = g_Gf + (size_t)bn * BN * KDIM;

    float acc[4][8][4];
    #pragma unroll
    for (int a = 0; a < 4; ++a)
        #pragma unroll
        for (int b = 0; b < 8; ++b)
            #pragma unroll
            for (int c = 0; c < 4; ++c) acc[a][b][c] = 0.f;

    auto loadStage = [&](int ch, int st) {        // full stage (prologue only)
        const uint32_t sb = sm0 + (uint32_t)st * STAGE_BYTES;
        const int kc = ch * BK;
        #pragma unroll
        for (int t = 0; t < 8; ++t) {
            int q = tid + t * 128;
            int row = q >> 3, c = q & 7;
            cpa16(sb + S_A + swz(row, c * 16),
                  (const char*)(Ax + (size_t)row * KDIM + kc) + c * 16);
        }
        #pragma unroll
        for (int t = 0; t < 8; ++t) {
            int q = tid + t * 128;
            int row = q >> 3, c = q & 7;
            cpa16(sb + S_B + swz(row, c * 16),
                  (const char*)(Bg + (size_t)row * KDIM + kc) + c * 16);
        }
    };

    auto loadQuarter = [&](int ch, int st, int qt) {   // 1/4 of a stage (2 A + 2 B iters)
        const uint32_t sb = sm0 + (uint32_t)st * STAGE_BYTES;
        const int kc = ch * BK;
        #pragma unroll
        for (int t = qt * 2; t < qt * 2 + 2; ++t) {
            int q = tid + t * 128;
            int row = q >> 3, c = q & 7;
            cpa16(sb + S_A + swz(row, c * 16),
                  (const char*)(Ax + (size_t)row * KDIM + kc) + c * 16);
        }
        #pragma unroll
        for (int t = qt * 2; t < qt * 2 + 2; ++t) {
            int q = tid + t * 128;
            int row = q >> 3, c = q & 7;
            cpa16(sb + S_B + swz(row, c * 16),
                  (const char*)(Bg + (size_t)row * KDIM + kc) + c * 16);
        }
    };

    auto loadAfrag = [&](uint32_t (*dst)[4], uint32_t sb, int kk) {
        #pragma unroll
        for (int im = 0; im < 4; ++im) {
            int row = wm * 64 + im * 16 + (lane & 15);
            int byte = kk * 2 + ((lane >> 4) << 4);
            ldmx4(dst[im], sb + S_A + swz(row, byte));
        }
    };
    auto loadBfrag = [&](uint32_t* dst, uint32_t sb, int kk, int jp) {
        int nrow = wn * 64 + (jp * 2 + (lane >> 4)) * 8 + (lane & 7);
        int byte = kk * 2 + (((lane >> 3) & 1) << 4);
        ldmx4(dst, sb + S_B + swz(nrow, byte));
    };

    // prologue: stages 0,1
    loadStage(0, 0);
    asm volatile("cp.async.commit_group;");
    loadStage(1, 1);
    asm volatile("cp.async.commit_group;");

    int cur = 0, nxt = 2;
    for (int ch = 0; ch < NCH; ++ch) {
        asm volatile("cp.async.wait_group 1;");
        __syncthreads();

        const uint32_t sb = sm0 + (uint32_t)cur * STAGE_BYTES;
        const bool doLoad = (ch + 2 < NCH);
        const int ldch = ch + 2, ldst = nxt;
        cur = (cur == 2) ? 0 : cur + 1;
        nxt = (nxt == 2) ? 0 : nxt + 1;

        uint32_t avA[4][4], avB[4][4];
        uint32_t bvA[4], bvB[4];
        loadAfrag(avA, sb, 0);                    // prefetch A for kk=0
        loadBfrag(bvA, sb, 0, 0);                 // prefetch B for kk=0, jp=0
        #pragma unroll
        for (int kki = 0; kki < 4; ++kki) {
            if (doLoad) loadQuarter(ldch, ldst, kki);      // spread next-stage loads
            if (kki == 3) asm volatile("cp.async.commit_group;");
            uint32_t (*avc)[4] = (kki & 1) ? avB : avA;
            uint32_t (*avn)[4] = (kki & 1) ? avA : avB;
            if (kki < 3) loadAfrag(avn, sb, (kki + 1) * 16);   // prefetch next k16 A
            const int kk = kki * 16;
            #pragma unroll
            for (int jp = 0; jp < 4; ++jp) {
                uint32_t* bvc = ((kki * 4 + jp) & 1) ? bvB : bvA;
                uint32_t* bvn = ((kki * 4 + jp) & 1) ? bvA : bvB;
                if (jp < 3)            loadBfrag(bvn, sb, kk, jp + 1);
                else if (kki < 3)      loadBfrag(bvn, sb, kk + 16, 0);
                #pragma unroll
                for (int im = 0; im < 4; ++im) {
                    mma16816(acc[im][jp * 2],     avc[im], bvc[0], bvc[1]);
                    mma16816(acc[im][jp * 2 + 1], avc[im], bvc[2], bvc[3]);
                }
            }
        }
    }

    // ---- epilogue: add bias, store fp32 ----
    #pragma unroll
    for (int im = 0; im < 4; ++im) {
        int r0 = bm * BM + wm * 64 + im * 16 + (lane >> 2);
        #pragma unroll
        for (int jn = 0; jn < 8; ++jn) {
            int cb = bn * BN + wn * 64 + jn * 8 + (lane & 3) * 2;
            float b0 = bias[cb], b1 = bias[cb + 1];
            float2 v0, v1;
            v0.x = acc[im][jn][0] + b0; v0.y = acc[im][jn][1] + b1;
            v1.x = acc[im][jn][2] + b0; v1.y = acc[im][jn][3] + b1;
            *reinterpret_cast<float2*>(C + (size_t)r0 * NDIM + cb) = v0;
            *reinterpret_cast<float2*>(C + (size_t)(r0 + 8) * NDIM + cb) = v1;
        }
    }
}

// ---------------- launch ----------------
extern "C" void kernel_launch(void* const* d_in, const int* in_sizes, int n_in,
                              void* d_out, int out_size) {
    const float* x     = (const float*)d_in[0];
    const float* core0 = (const float*)d_in[1];
    const float* core1 = (const float*)d_in[2];
    const float* core2 = (const float*)d_in[3];
    const float* bias  = (const float*)d_in[4];
    float* out = (float*)d_out;

    // 1024 build-G blocks (k split 4-ways) + 2048 conv blocks (16 float4/thread)
    prep<<<1024 + NB_CONV, 256>>>(core0, core1, core2, x);

    cudaFuncSetAttribute(gemm_pipe, cudaFuncAttributeMaxDynamicSharedMemorySize, SMEM_BYTES);
    dim3 grid(NDIM / BN, MDIM / BM);     // (32, 64), x-fastest keeps G hot in L2
    gemm_pipe<<<grid, 128, SMEM_BYTES>>>(bias, out);
}